// round 5
// baseline (speedup 1.0000x reference)
#include <cuda_runtime.h>

#define Nn   20000
#define PADR 128
#define Ee   640000
#define ENt  660000      // edges + self loops
#define INFt 2048
#define OMt  512
#define NCt  8192
#define C1t  256
#define C2t  128
#define EPSf 1e-5f

// ---------------- device scratch (static, no allocation) ----------------
__device__ int   g_ei64, g_sm64;
__device__ int   d_ROW[ENt], d_COL[ENt];
__device__ float d_deg[Nn], d_dinv[Nn];
__device__ int   d_ecnt[Nn], d_fillc[Nn], d_indptr[Nn + 1];
__device__ int   d_src[ENt];
__device__ float d_cw[ENt];
__device__ int   d_mcnt[OMt], d_mfill[OMt], d_mptr[OMt + 1];
__device__ int   d_min_[NCt], d_mout[NCt], d_sin[NCt];
__device__ float d_mw[NCt], d_sw[NCt];
__device__ float d_h0[(size_t)(Nn + PADR) * OMt];
__device__ float d_g1[(size_t)(Nn + PADR) * C1t], d_h1[(size_t)(Nn + PADR) * C1t];
__device__ float d_g2[(size_t)(Nn + PADR) * C2t], d_h2[(size_t)(Nn + PADR) * C2t];
__device__ float d_sum0[OMt], d_sq0[OMt], d_sum1[C1t], d_sq1[C1t], d_sum2[C2t], d_sq2[C2t];
__device__ float d_W1f[OMt * C1t], d_c1[C1t];
__device__ float d_W2f[C1t * C2t], d_c2[C2t];
__device__ float d_Wlf[C2t * 2],  d_c3[2];

// ---------------- dtype sniffing: int64 vs int32 index arrays ----------------
__global__ void k_detect(const unsigned* ei, const unsigned* sm) {
    __shared__ int f0, f1;
    int t = threadIdx.x;
    if (t == 0) { f0 = 0; f1 = 0; }
    __syncthreads();
    if (t < 128) {
        if (ei[2 * t + 1]) atomicOr(&f0, 1);
        if (sm[2 * t + 1]) atomicOr(&f1, 1);
    }
    __syncthreads();
    if (t == 0) { g_ei64 = (f0 == 0); g_sm64 = (f1 == 0); }
}

__global__ void k_zero() {
    int i = blockIdx.x * blockDim.x + threadIdx.x;
    if (i < Nn)  { d_deg[i] = 0.f; d_ecnt[i] = 0; d_fillc[i] = 0; }
    if (i < OMt) { d_mcnt[i] = 0; d_mfill[i] = 0; d_sum0[i] = 0.f; d_sq0[i] = 0.f; }
    if (i < C1t) { d_sum1[i] = 0.f; d_sq1[i] = 0.f; }
    if (i < C2t) { d_sum2[i] = 0.f; d_sq2[i] = 0.f; }
}

// merged: edge decode+count (blocks [0,EB)) and mask decode+count (blocks [EB,EB+MB))
#define EB 2579
#define MB 32
__global__ void k_edges_mask(const void* eiv, const float* __restrict__ ew,
                             const void* smv, const float* __restrict__ smw) {
    if (blockIdx.x < EB) {
        int e = blockIdx.x * blockDim.x + threadIdx.x;
        if (e >= ENt) return;
        int r, c;
        if (e < Ee) {
            if (g_ei64) {
                const long long* p = (const long long*)eiv;
                r = (int)p[e]; c = (int)p[Ee + e];
            } else {
                const int* p = (const int*)eiv;
                r = p[e]; c = p[Ee + e];
            }
        } else { r = c = e - Ee; }
        float w = (e < Ee) ? ew[e] : 1.f;
        d_ROW[e] = r; d_COL[e] = c;
        atomicAdd(&d_deg[c], w);
        atomicAdd(&d_ecnt[c], 1);
    } else {
        int j = (blockIdx.x - EB) * blockDim.x + threadIdx.x;
        if (j >= NCt) return;
        int a, b;
        if (g_sm64) {
            const long long* p = (const long long*)smv;
            a = (int)p[2 * j]; b = (int)p[2 * j + 1];
        } else {
            const int* p = (const int*)smv;
            a = p[2 * j]; b = p[2 * j + 1];
        }
        d_min_[j] = a; d_mout[j] = b; d_mw[j] = smw[j];
        atomicAdd(&d_mcnt[b], 1);
    }
}

// single block: dinv + indptr scan (20000) + mask ptr scan (512)
__global__ void k_scan_dinv() {
    __shared__ int sh[1024];
    const int CH = 20;
    int t = threadIdx.x;
#pragma unroll
    for (int i = 0; i < CH; i++) {
        int idx = t * CH + i;
        if (idx < Nn) { float dg = d_deg[idx]; d_dinv[idx] = (dg > 0.f) ? rsqrtf(dg) : 0.f; }
    }
    int base = t * CH, loc = 0;
    int cnts[CH];
#pragma unroll
    for (int i = 0; i < CH; i++) {
        int idx = base + i;
        int v = (idx < Nn) ? d_ecnt[idx] : 0;
        cnts[i] = v; loc += v;
    }
    sh[t] = loc; __syncthreads();
    for (int off = 1; off < 1024; off <<= 1) {
        int v = (t >= off) ? sh[t - off] : 0;
        __syncthreads();
        sh[t] += v;
        __syncthreads();
    }
    int run = sh[t] - loc;
#pragma unroll
    for (int i = 0; i < CH; i++) {
        int idx = base + i;
        if (idx < Nn) d_indptr[idx] = run;
        run += cnts[i];
    }
    if (t == 1023) d_indptr[Nn] = sh[1023];
    __syncthreads();
    int v2 = (t < OMt) ? d_mcnt[t] : 0;
    sh[t] = v2; __syncthreads();
    for (int off = 1; off < OMt; off <<= 1) {
        int v = (t >= off) ? sh[t - off] : 0;
        __syncthreads();
        sh[t] += v;
        __syncthreads();
    }
    if (t < OMt) d_mptr[t] = sh[t] - v2;
    if (t == OMt - 1) d_mptr[OMt] = sh[t];
}

__global__ void k_fill_mfill(const float* __restrict__ ew) {
    if (blockIdx.x < EB) {
        int e = blockIdx.x * blockDim.x + threadIdx.x;
        if (e >= ENt) return;
        int c = d_COL[e], r = d_ROW[e];
        int p = d_indptr[c] + atomicAdd(&d_fillc[c], 1);
        float w = (e < Ee) ? ew[e] : 1.f;
        d_src[p] = r;
        d_cw[p] = d_dinv[r] * w * d_dinv[c];
    } else {
        int j = (blockIdx.x - EB) * blockDim.x + threadIdx.x;
        if (j >= NCt) return;
        int b = d_mout[j];
        int p = d_mptr[b] + atomicAdd(&d_mfill[b], 1);
        d_sin[p] = d_min_[j];
        d_sw[p] = d_mw[j];
    }
}

// ---------------- stage A: sparse masked linear + ReLU + fused column stats ----------------
#define NPB 4
__global__ void __launch_bounds__(512) k_stageA(const float* __restrict__ x,
                                                const float* __restrict__ smb) {
    __shared__ float xs[NPB][INFt];
    int node0 = blockIdx.x * NPB;
    int t = threadIdx.x;
    const float4* xg = (const float4*)(x + (size_t)node0 * INFt);
    float4* xsv = (float4*)xs;
#pragma unroll
    for (int i = 0; i < (NPB * INFt / 4) / 512; i++)
        xsv[t + i * 512] = xg[t + i * 512];
    __syncthreads();
    int o = t;
    float a0 = 0.f, a1 = 0.f, a2 = 0.f, a3 = 0.f;
    int p0 = d_mptr[o], p1 = d_mptr[o + 1];
    for (int p = p0; p < p1; p++) {
        int idx = d_sin[p];
        float w = d_sw[p];
        a0 += xs[0][idx] * w;
        a1 += xs[1][idx] * w;
        a2 += xs[2][idx] * w;
        a3 += xs[3][idx] * w;
    }
    float b = smb[o];
    float v0 = fmaxf(a0 + b, 0.f);
    float v1 = fmaxf(a1 + b, 0.f);
    float v2 = fmaxf(a2 + b, 0.f);
    float v3 = fmaxf(a3 + b, 0.f);
    d_h0[(size_t)(node0 + 0) * OMt + o] = v0;
    d_h0[(size_t)(node0 + 1) * OMt + o] = v1;
    d_h0[(size_t)(node0 + 2) * OMt + o] = v2;
    d_h0[(size_t)(node0 + 3) * OMt + o] = v3;
    atomicAdd(&d_sum0[o], v0 + v1 + v2 + v3);
    atomicAdd(&d_sq0[o], v0 * v0 + v1 * v1 + v2 * v2 + v3 * v3);
}

// ---------------- merged BN-fold: Wf = a⊙W (rows), c = d@W (+addb) ----------------
__global__ void __launch_bounds__(256) k_prep(
    const float* __restrict__ W, const float* __restrict__ sum,
    const float* __restrict__ sq, const float* __restrict__ g,
    const float* __restrict__ b, const float* __restrict__ addb,
    float* __restrict__ Wf, float* __restrict__ cvec, int Kd, int Nd) {
    int t = threadIdx.x;
    if (blockIdx.x + 1 < gridDim.x) {
        int i = blockIdx.x * 256 + t;
        if (i < Kd * Nd) {
            int k = i / Nd;
            float m = sum[k] * (1.f / Nn);
            float v = fmaxf(sq[k] * (1.f / Nn) - m * m, 0.f);
            float s = g[k] * rsqrtf(v + EPSf);
            Wf[i] = s * W[i];
        }
    } else {
        __shared__ float dsh[512];
        for (int k = t; k < Kd; k += 256) {
            float m = sum[k] * (1.f / Nn);
            float v = fmaxf(sq[k] * (1.f / Nn) - m * m, 0.f);
            float s = g[k] * rsqrtf(v + EPSf);
            dsh[k] = b[k] - m * s;
        }
        __syncthreads();
        if (t < Nd) {
            float s = addb ? addb[t] : 0.f;
            for (int k = 0; k < Kd; k++) s += dsh[k] * W[k * Nd + t];
            cvec[t] = s;
        }
    }
}

// ---------------- SGEMM: C[M,Nd] = A[M,K]@B[K,Nd]  (128x128 tile, 8x8 micro) ----------------
// A, C are padded to Nn+PADR rows -> no row guards needed.
__global__ void __launch_bounds__(256, 2)
k_gemm(const float* __restrict__ A, const float* __restrict__ B,
       float* __restrict__ C, int K, int Nd) {
    __shared__ __align__(16) float As[16][128];   // As[k][m]
    __shared__ __align__(16) float Bs[16][128];   // Bs[k][n]
    int t = threadIdx.x;
    int tx = t & 15, ty = t >> 4;
    int mb = blockIdx.x * 128, nb = blockIdx.y * 128;
    float c[8][8];
#pragma unroll
    for (int i = 0; i < 8; i++)
#pragma unroll
        for (int j = 0; j < 8; j++) c[i][j] = 0.f;

    for (int kt = 0; kt < K; kt += 16) {
#pragma unroll
        for (int i = 0; i < 2; i++) {
            int li = t + i * 256;
            int row = li >> 2, kq = li & 3;
            float4 v = *(const float4*)(A + (size_t)(mb + row) * K + kt + kq * 4);
            int kk = kq * 4;
            As[kk + 0][row] = v.x;
            As[kk + 1][row] = v.y;
            As[kk + 2][row] = v.z;
            As[kk + 3][row] = v.w;
        }
#pragma unroll
        for (int i = 0; i < 2; i++) {
            int li = t + i * 256;
            int kr = li >> 5, jq = li & 31;
            *(float4*)&Bs[kr][jq * 4] =
                *(const float4*)(B + (size_t)(kt + kr) * Nd + nb + jq * 4);
        }
        __syncthreads();
#pragma unroll
        for (int k = 0; k < 16; k++) {
            float4 a0 = *(const float4*)&As[k][ty * 8];
            float4 a1 = *(const float4*)&As[k][ty * 8 + 4];
            float4 b0 = *(const float4*)&Bs[k][tx * 8];
            float4 b1 = *(const float4*)&Bs[k][tx * 8 + 4];
            float av[8] = {a0.x, a0.y, a0.z, a0.w, a1.x, a1.y, a1.z, a1.w};
            float bv[8] = {b0.x, b0.y, b0.z, b0.w, b1.x, b1.y, b1.z, b1.w};
#pragma unroll
            for (int i = 0; i < 8; i++)
#pragma unroll
                for (int j = 0; j < 8; j++) c[i][j] = fmaf(av[i], bv[j], c[i][j]);
        }
        __syncthreads();
    }
#pragma unroll
    for (int i = 0; i < 8; i++) {
        int m = mb + ty * 8 + i;
#pragma unroll
        for (int j = 0; j < 2; j++) {
            int col = nb + tx * 8 + j * 4;
            *(float4*)(C + (size_t)m * Nd + col) = *(float4*)&c[i][j * 4];
        }
    }
}

// ---------------- CSR agg: out[n]=relu(sum w*g[src] + (sum w)*cv + bias), fused stats ----------------
__global__ void k_agg(const float* __restrict__ g, const float* __restrict__ cv,
                      const float* __restrict__ bias, float* __restrict__ out,
                      float* __restrict__ sum, float* __restrict__ sq, int F) {
    int n = blockIdx.x, t = threadIdx.x;
    int s0 = d_indptr[n], s1 = d_indptr[n + 1];
    float acc = 0.f, ws = 0.f;
    for (int e = s0; e < s1; e++) {
        int s = __ldg(&d_src[e]);
        float w = __ldg(&d_cw[e]);
        ws += w;
        acc += g[(size_t)s * F + t] * w;
    }
    float v = fmaxf(acc + ws * cv[t] + bias[t], 0.f);
    out[(size_t)n * F + t] = v;
    atomicAdd(&sum[t], v);
    atomicAdd(&sq[t], v * v);
}

// ---------------- final linear: out[n,:2] = h2[n,:] @ Wlf + c3 ----------------
__global__ void k_final(float* __restrict__ out) {
    int w = blockIdx.x * 8 + (threadIdx.x >> 5);
    int lane = threadIdx.x & 31;
    if (w >= Nn) return;
    float4 v = ((const float4*)(d_h2 + (size_t)w * C2t))[lane];
    float4 w0 = ((const float4*)d_Wlf)[lane * 2];
    float4 w1 = ((const float4*)d_Wlf)[lane * 2 + 1];
    float s0 = v.x * w0.x + v.y * w0.z + v.z * w1.x + v.w * w1.z;
    float s1 = v.x * w0.y + v.y * w0.w + v.z * w1.y + v.w * w1.w;
#pragma unroll
    for (int off = 16; off; off >>= 1) {
        s0 += __shfl_down_sync(0xffffffffu, s0, off);
        s1 += __shfl_down_sync(0xffffffffu, s1, off);
    }
    if (lane == 0) {
        out[w * 2 + 0] = s0 + d_c3[0];
        out[w * 2 + 1] = s1 + d_c3[1];
    }
}

// ---------------- host launch ----------------
extern "C" void kernel_launch(void* const* d_in, const int* in_sizes, int n_in,
                              void* d_out, int out_size) {
    const float* x     = (const float*)d_in[0];
    const void*  ei    = d_in[1];
    const float* ew    = (const float*)d_in[2];
    const void*  sm    = d_in[3];
    const float* smw   = (const float*)d_in[4];
    const float* smb   = (const float*)d_in[5];
    const float* bnsg  = (const float*)d_in[6];
    const float* bnsb  = (const float*)d_in[7];
    const float* W1    = (const float*)d_in[8];
    const float* b1    = (const float*)d_in[9];
    const float* bn1g  = (const float*)d_in[10];
    const float* bn1b  = (const float*)d_in[11];
    const float* W2    = (const float*)d_in[12];
    const float* b2    = (const float*)d_in[13];
    const float* bn2g  = (const float*)d_in[14];
    const float* bn2b  = (const float*)d_in[15];
    const float* linW  = (const float*)d_in[16];
    const float* linb  = (const float*)d_in[17];
    float* out = (float*)d_out;

    float *p_h0, *p_g1, *p_h1, *p_g2, *p_h2;
    float *p_W1f, *p_W2f, *p_Wlf, *p_c1, *p_c2, *p_c3;
    float *p_s0, *p_q0, *p_s1, *p_q1, *p_s2, *p_q2;
    cudaGetSymbolAddress((void**)&p_h0, d_h0);
    cudaGetSymbolAddress((void**)&p_g1, d_g1);
    cudaGetSymbolAddress((void**)&p_h1, d_h1);
    cudaGetSymbolAddress((void**)&p_g2, d_g2);
    cudaGetSymbolAddress((void**)&p_h2, d_h2);
    cudaGetSymbolAddress((void**)&p_W1f, d_W1f);
    cudaGetSymbolAddress((void**)&p_W2f, d_W2f);
    cudaGetSymbolAddress((void**)&p_Wlf, d_Wlf);
    cudaGetSymbolAddress((void**)&p_c1, d_c1);
    cudaGetSymbolAddress((void**)&p_c2, d_c2);
    cudaGetSymbolAddress((void**)&p_c3, d_c3);
    cudaGetSymbolAddress((void**)&p_s0, d_sum0);
    cudaGetSymbolAddress((void**)&p_q0, d_sq0);
    cudaGetSymbolAddress((void**)&p_s1, d_sum1);
    cudaGetSymbolAddress((void**)&p_q1, d_sq1);
    cudaGetSymbolAddress((void**)&p_s2, d_sum2);
    cudaGetSymbolAddress((void**)&p_q2, d_sq2);

    k_detect<<<1, 128>>>((const unsigned*)ei, (const unsigned*)sm);        // 1
    k_zero<<<(Nn + 255) / 256, 256>>>();                                   // 2
    k_edges_mask<<<EB + MB, 256>>>(ei, ew, sm, smw);                       // 3
    k_scan_dinv<<<1, 1024>>>();                                            // 4
    k_fill_mfill<<<EB + MB, 256>>>(ew);                                    // 5

    k_stageA<<<Nn / NPB, 512>>>(x, smb);                                   // 6 (ncu capture)

    k_prep<<<(OMt * C1t + 255) / 256 + 1, 256>>>(W1, p_s0, p_q0, bnsg, bnsb,
                                                 nullptr, p_W1f, p_c1, OMt, C1t);
    k_gemm<<<dim3((Nn + 127) / 128, C1t / 128), 256>>>(p_h0, p_W1f, p_g1, OMt, C1t);
    k_agg<<<Nn, C1t>>>(p_g1, p_c1, b1, p_h1, p_s1, p_q1, C1t);

    k_prep<<<(C1t * C2t + 255) / 256 + 1, 256>>>(W2, p_s1, p_q1, bn1g, bn1b,
                                                 nullptr, p_W2f, p_c2, C1t, C2t);
    k_gemm<<<dim3((Nn + 127) / 128, C2t / 128), 256>>>(p_h1, p_W2f, p_g2, C1t, C2t);
    k_agg<<<Nn, C2t>>>(p_g2, p_c2, b2, p_h2, p_s2, p_q2, C2t);

    k_prep<<<2, 256>>>(linW, p_s2, p_q2, bn2g, bn2b, linb, p_Wlf, p_c3, C2t, 2);
    k_final<<<(Nn + 7) / 8, 256>>>(out);
}

// round 6
// speedup vs baseline: 1.2179x; 1.2179x over previous
#include <cuda_runtime.h>

#define Nn   20000
#define PADR 128
#define Ee   640000
#define ENt  660000      // edges + self loops
#define INFt 2048
#define OMt  512
#define NCt  8192
#define C1t  256
#define C2t  128
#define EPSf 1e-5f

// ---------------- device scratch (static, no allocation) ----------------
__device__ int   g_ei64, g_sm64;
__device__ int   d_ROW[ENt], d_COL[ENt];
__device__ float d_deg[Nn], d_dinv[Nn];
__device__ int   d_ecnt[Nn], d_fillc[Nn], d_indptr[Nn + 1];
__device__ int   d_src[ENt];
__device__ float d_cw[ENt];
__device__ int   d_mcnt[OMt], d_mfill[OMt], d_mptr[OMt + 1];
__device__ int   d_min_[NCt], d_mout[NCt], d_sin[NCt];
__device__ float d_mw[NCt], d_sw[NCt];
__device__ float d_h0[(size_t)(Nn + PADR) * OMt];
__device__ float d_g1[(size_t)(Nn + PADR) * C1t], d_h1[(size_t)(Nn + PADR) * C1t];
__device__ float d_g2[(size_t)(Nn + PADR) * C2t], d_h2[(size_t)(Nn + PADR) * C2t];
__device__ float d_sum0[OMt], d_sq0[OMt], d_sum1[C1t], d_sq1[C1t], d_sum2[C2t], d_sq2[C2t];
__device__ float d_W1f[OMt * C1t], d_c1[C1t];
__device__ float d_W2f[C1t * C2t], d_c2[C2t];
__device__ float d_Wlf[C2t * 2],  d_c3[2];

// ---------------- 1: dtype sniff + zero mask counters ----------------
__global__ void k_detect(const unsigned* ei, const unsigned* sm) {
    __shared__ int f0, f1;
    int t = threadIdx.x;
    if (t == 0) { f0 = 0; f1 = 0; }
    __syncthreads();
    if (t < 128) {
        if (ei[2 * t + 1]) atomicOr(&f0, 1);
        if (sm[2 * t + 1]) atomicOr(&f1, 1);
    }
    for (int i = t; i < OMt; i += 128) { d_mcnt[i] = 0; d_mfill[i] = 0; }
    __syncthreads();
    if (t == 0) { g_ei64 = (f0 == 0); g_sm64 = (f1 == 0); }
}

// ---------------- 2: decode sparse mask + count per out column ----------------
__global__ void k_maskcount(const void* smv, const float* __restrict__ smw) {
    int j = blockIdx.x * blockDim.x + threadIdx.x;
    if (j >= NCt) return;
    int a, b;
    if (g_sm64) {
        const long long* p = (const long long*)smv;
        a = (int)p[2 * j]; b = (int)p[2 * j + 1];
    } else {
        const int* p = (const int*)smv;
        a = p[2 * j]; b = p[2 * j + 1];
    }
    d_min_[j] = a; d_mout[j] = b; d_mw[j] = smw[j];
    atomicAdd(&d_mcnt[b], 1);
}

// ---------------- 3: single block: scan 512 mask counts + CSC fill ----------------
__global__ void __launch_bounds__(512) k_mask_scanfill() {
    __shared__ int wsum[16];
    int t = threadIdx.x;
    int lane = t & 31, warp = t >> 5;
    int v = d_mcnt[t];
    int s = v;
#pragma unroll
    for (int off = 1; off < 32; off <<= 1) {
        int u = __shfl_up_sync(~0u, s, off);
        if (lane >= off) s += u;
    }
    if (lane == 31) wsum[warp] = s;
    __syncthreads();
    if (warp == 0 && lane < 16) {
        int w = wsum[lane];
#pragma unroll
        for (int off = 1; off < 16; off <<= 1) {
            int u = __shfl_up_sync(0xffffu, w, off);
            if (lane >= off) w += u;
        }
        wsum[lane] = w;
    }
    __syncthreads();
    int incl = s + (warp ? wsum[warp - 1] : 0);
    d_mptr[t] = incl - v;
    if (t == 511) d_mptr[OMt] = incl;
    __syncthreads();
    for (int j = t; j < NCt; j += 512) {
        int b = d_mout[j];
        int p = d_mptr[b] + atomicAdd(&d_mfill[b], 1);
        d_sin[p] = d_min_[j];
        d_sw[p] = d_mw[j];
    }
}

// ---------------- 4 (PROFILED): sparse masked linear + ReLU ----------------
#define NPB 4
__global__ void __launch_bounds__(512) k_stageA(const float* __restrict__ x,
                                                const float* __restrict__ smb) {
    __shared__ float xs[NPB][INFt];
    int node0 = blockIdx.x * NPB;
    int t = threadIdx.x;
    const float4* xg = (const float4*)(x + (size_t)node0 * INFt);
    float4* xsv = (float4*)xs;
#pragma unroll
    for (int i = 0; i < (NPB * INFt / 4) / 512; i++)
        xsv[t + i * 512] = xg[t + i * 512];
    __syncthreads();
    int o = t;
    float a0 = 0.f, a1 = 0.f, a2 = 0.f, a3 = 0.f;
    int p0 = d_mptr[o], p1 = d_mptr[o + 1];
    for (int p = p0; p < p1; p++) {
        int idx = d_sin[p];
        float w = d_sw[p];
        a0 += xs[0][idx] * w;
        a1 += xs[1][idx] * w;
        a2 += xs[2][idx] * w;
        a3 += xs[3][idx] * w;
    }
    float b = smb[o];
    d_h0[(size_t)(node0 + 0) * OMt + o] = fmaxf(a0 + b, 0.f);
    d_h0[(size_t)(node0 + 1) * OMt + o] = fmaxf(a1 + b, 0.f);
    d_h0[(size_t)(node0 + 2) * OMt + o] = fmaxf(a2 + b, 0.f);
    d_h0[(size_t)(node0 + 3) * OMt + o] = fmaxf(a3 + b, 0.f);
}

// ---------------- 5: zero edge counters + BN accumulators ----------------
__global__ void k_zero() {
    int i = blockIdx.x * blockDim.x + threadIdx.x;
    if (i < Nn)  { d_deg[i] = 0.f; d_ecnt[i] = 0; d_fillc[i] = 0; }
    if (i < OMt) { d_sum0[i] = 0.f; d_sq0[i] = 0.f; }
    if (i < C1t) { d_sum1[i] = 0.f; d_sq1[i] = 0.f; }
    if (i < C2t) { d_sum2[i] = 0.f; d_sq2[i] = 0.f; }
}

// ---------------- 6: decode edges + per-col degree/count ----------------
__global__ void k_edges(const void* eiv, const float* __restrict__ ew) {
    int e = blockIdx.x * blockDim.x + threadIdx.x;
    if (e >= ENt) return;
    int r, c;
    if (e < Ee) {
        if (g_ei64) {
            const long long* p = (const long long*)eiv;
            r = (int)p[e]; c = (int)p[Ee + e];
        } else {
            const int* p = (const int*)eiv;
            r = p[e]; c = p[Ee + e];
        }
    } else { r = c = e - Ee; }
    float w = (e < Ee) ? ew[e] : 1.f;
    d_ROW[e] = r; d_COL[e] = c;
    atomicAdd(&d_deg[c], w);
    atomicAdd(&d_ecnt[c], 1);
}

// ---------------- 7: shuffle-scan indptr (20000) + dinv ----------------
__global__ void __launch_bounds__(1024) k_scan_dinv() {
    __shared__ int wsum[32];
    const int CH = 20;
    int t = threadIdx.x;
    int lane = t & 31, warp = t >> 5;
    int base = t * CH;
    int cnts[CH];
    int loc = 0;
#pragma unroll
    for (int i = 0; i < CH; i++) {
        int v = (base + i < Nn) ? __ldg(&d_ecnt[base + i]) : 0;
        cnts[i] = v; loc += v;
    }
    int s = loc;
#pragma unroll
    for (int off = 1; off < 32; off <<= 1) {
        int u = __shfl_up_sync(~0u, s, off);
        if (lane >= off) s += u;
    }
    if (lane == 31) wsum[warp] = s;
    __syncthreads();
    if (warp == 0) {
        int w = wsum[lane];
#pragma unroll
        for (int off = 1; off < 32; off <<= 1) {
            int u = __shfl_up_sync(~0u, w, off);
            if (lane >= off) w += u;
        }
        wsum[lane] = w;
    }
    __syncthreads();
    int run = s - loc + (warp ? wsum[warp - 1] : 0);
#pragma unroll
    for (int i = 0; i < CH; i++) {
        if (base + i < Nn) d_indptr[base + i] = run;
        run += cnts[i];
    }
    if (t == 1023) d_indptr[Nn] = run;
    for (int i = t; i < Nn; i += 1024) {
        float dg = d_deg[i];
        d_dinv[i] = (dg > 0.f) ? rsqrtf(dg) : 0.f;
    }
}

// ---------------- 8: CSR fill with normalized weights ----------------
__global__ void k_fill(const float* __restrict__ ew) {
    int e = blockIdx.x * blockDim.x + threadIdx.x;
    if (e >= ENt) return;
    int c = d_COL[e], r = d_ROW[e];
    int p = d_indptr[c] + atomicAdd(&d_fillc[c], 1);
    float w = (e < Ee) ? ew[e] : 1.f;
    d_src[p] = r;
    d_cw[p] = d_dinv[r] * w * d_dinv[c];
}

// ---------------- column stats (low-contention: 256 blocks) ----------------
__global__ void k_stats(const float* __restrict__ in, float* __restrict__ sum,
                        float* __restrict__ sq, int F) {
    int t = threadIdx.x;   // blockDim == F
    float s = 0.f, q = 0.f;
    for (int r = blockIdx.x; r < Nn; r += gridDim.x) {
        float v = in[(size_t)r * F + t];
        s += v; q += v * v;
    }
    atomicAdd(&sum[t], s);
    atomicAdd(&sq[t], q);
}

// ---------------- merged BN-fold: Wf = a⊙W (rows), c = d@W (+addb) ----------------
__global__ void __launch_bounds__(256) k_prep(
    const float* __restrict__ W, const float* __restrict__ sum,
    const float* __restrict__ sq, const float* __restrict__ g,
    const float* __restrict__ b, const float* __restrict__ addb,
    float* __restrict__ Wf, float* __restrict__ cvec, int Kd, int Nd) {
    int t = threadIdx.x;
    if (blockIdx.x + 1 < gridDim.x) {
        int i = blockIdx.x * 256 + t;
        if (i < Kd * Nd) {
            int k = i / Nd;
            float m = sum[k] * (1.f / Nn);
            float v = fmaxf(sq[k] * (1.f / Nn) - m * m, 0.f);
            float s = g[k] * rsqrtf(v + EPSf);
            Wf[i] = s * W[i];
        }
    } else {
        __shared__ float dsh[512];
        for (int k = t; k < Kd; k += 256) {
            float m = sum[k] * (1.f / Nn);
            float v = fmaxf(sq[k] * (1.f / Nn) - m * m, 0.f);
            float s = g[k] * rsqrtf(v + EPSf);
            dsh[k] = b[k] - m * s;
        }
        __syncthreads();
        if (t < Nd) {
            float s = addb ? addb[t] : 0.f;
            for (int k = 0; k < Kd; k++) s += dsh[k] * W[k * Nd + t];
            cvec[t] = s;
        }
    }
}

// ---------------- SGEMM: C[M,Nd] = A[M,K]@B[K,Nd]  (128x128 tile, 8x8 micro) ----------------
// A, C padded to Nn+PADR rows -> no row guards.
__global__ void __launch_bounds__(256, 2)
k_gemm(const float* __restrict__ A, const float* __restrict__ B,
       float* __restrict__ C, int K, int Nd) {
    __shared__ __align__(16) float As[16][128];
    __shared__ __align__(16) float Bs[16][128];
    int t = threadIdx.x;
    int tx = t & 15, ty = t >> 4;
    int mb = blockIdx.x * 128, nb = blockIdx.y * 128;
    float c[8][8];
#pragma unroll
    for (int i = 0; i < 8; i++)
#pragma unroll
        for (int j = 0; j < 8; j++) c[i][j] = 0.f;

    for (int kt = 0; kt < K; kt += 16) {
#pragma unroll
        for (int i = 0; i < 2; i++) {
            int li = t + i * 256;
            int row = li >> 2, kq = li & 3;
            float4 v = *(const float4*)(A + (size_t)(mb + row) * K + kt + kq * 4);
            int kk = kq * 4;
            As[kk + 0][row] = v.x;
            As[kk + 1][row] = v.y;
            As[kk + 2][row] = v.z;
            As[kk + 3][row] = v.w;
        }
#pragma unroll
        for (int i = 0; i < 2; i++) {
            int li = t + i * 256;
            int kr = li >> 5, jq = li & 31;
            *(float4*)&Bs[kr][jq * 4] =
                *(const float4*)(B + (size_t)(kt + kr) * Nd + nb + jq * 4);
        }
        __syncthreads();
#pragma unroll
        for (int k = 0; k < 16; k++) {
            float4 a0 = *(const float4*)&As[k][ty * 8];
            float4 a1 = *(const float4*)&As[k][ty * 8 + 4];
            float4 b0 = *(const float4*)&Bs[k][tx * 8];
            float4 b1 = *(const float4*)&Bs[k][tx * 8 + 4];
            float av[8] = {a0.x, a0.y, a0.z, a0.w, a1.x, a1.y, a1.z, a1.w};
            float bv[8] = {b0.x, b0.y, b0.z, b0.w, b1.x, b1.y, b1.z, b1.w};
#pragma unroll
            for (int i = 0; i < 8; i++)
#pragma unroll
                for (int j = 0; j < 8; j++) c[i][j] = fmaf(av[i], bv[j], c[i][j]);
        }
        __syncthreads();
    }
#pragma unroll
    for (int i = 0; i < 8; i++) {
        int m = mb + ty * 8 + i;
#pragma unroll
        for (int j = 0; j < 2; j++) {
            int col = nb + tx * 8 + j * 4;
            *(float4*)(C + (size_t)m * Nd + col) = *(float4*)&c[i][j * 4];
        }
    }
}

// ---------------- CSR agg: out[n] = relu(sum w*g[src] + (sum w)*cv + bias) ----------------
__global__ void k_agg(const float* __restrict__ g, const float* __restrict__ cv,
                      const float* __restrict__ bias, float* __restrict__ out, int F) {
    int n = blockIdx.x, t = threadIdx.x;
    int s0 = d_indptr[n], s1 = d_indptr[n + 1];
    float acc = 0.f, ws = 0.f;
    for (int e = s0; e < s1; e++) {
        int s = __ldg(&d_src[e]);
        float w = __ldg(&d_cw[e]);
        ws += w;
        acc += g[(size_t)s * F + t] * w;
    }
    out[(size_t)n * F + t] = fmaxf(acc + ws * cv[t] + bias[t], 0.f);
}

// ---------------- final linear: out[n,:2] = h2[n,:] @ Wlf + c3 ----------------
__global__ void k_final(float* __restrict__ out) {
    int w = blockIdx.x * 8 + (threadIdx.x >> 5);
    int lane = threadIdx.x & 31;
    if (w >= Nn) return;
    float4 v = ((const float4*)(d_h2 + (size_t)w * C2t))[lane];
    float4 w0 = ((const float4*)d_Wlf)[lane * 2];
    float4 w1 = ((const float4*)d_Wlf)[lane * 2 + 1];
    float s0 = v.x * w0.x + v.y * w0.z + v.z * w1.x + v.w * w1.z;
    float s1 = v.x * w0.y + v.y * w0.w + v.z * w1.y + v.w * w1.w;
#pragma unroll
    for (int off = 16; off; off >>= 1) {
        s0 += __shfl_down_sync(0xffffffffu, s0, off);
        s1 += __shfl_down_sync(0xffffffffu, s1, off);
    }
    if (lane == 0) {
        out[w * 2 + 0] = s0 + d_c3[0];
        out[w * 2 + 1] = s1 + d_c3[1];
    }
}

// ---------------- host launch ----------------
extern "C" void kernel_launch(void* const* d_in, const int* in_sizes, int n_in,
                              void* d_out, int out_size) {
    const float* x     = (const float*)d_in[0];
    const void*  ei    = d_in[1];
    const float* ew    = (const float*)d_in[2];
    const void*  sm    = d_in[3];
    const float* smw   = (const float*)d_in[4];
    const float* smb   = (const float*)d_in[5];
    const float* bnsg  = (const float*)d_in[6];
    const float* bnsb  = (const float*)d_in[7];
    const float* W1    = (const float*)d_in[8];
    const float* b1    = (const float*)d_in[9];
    const float* bn1g  = (const float*)d_in[10];
    const float* bn1b  = (const float*)d_in[11];
    const float* W2    = (const float*)d_in[12];
    const float* b2    = (const float*)d_in[13];
    const float* bn2g  = (const float*)d_in[14];
    const float* bn2b  = (const float*)d_in[15];
    const float* linW  = (const float*)d_in[16];
    const float* linb  = (const float*)d_in[17];
    float* out = (float*)d_out;

    float *p_h0, *p_g1, *p_h1, *p_g2, *p_h2;
    float *p_W1f, *p_W2f, *p_Wlf, *p_c1, *p_c2, *p_c3;
    float *p_s0, *p_q0, *p_s1, *p_q1, *p_s2, *p_q2;
    cudaGetSymbolAddress((void**)&p_h0, d_h0);
    cudaGetSymbolAddress((void**)&p_g1, d_g1);
    cudaGetSymbolAddress((void**)&p_h1, d_h1);
    cudaGetSymbolAddress((void**)&p_g2, d_g2);
    cudaGetSymbolAddress((void**)&p_h2, d_h2);
    cudaGetSymbolAddress((void**)&p_W1f, d_W1f);
    cudaGetSymbolAddress((void**)&p_W2f, d_W2f);
    cudaGetSymbolAddress((void**)&p_Wlf, d_Wlf);
    cudaGetSymbolAddress((void**)&p_c1, d_c1);
    cudaGetSymbolAddress((void**)&p_c2, d_c2);
    cudaGetSymbolAddress((void**)&p_c3, d_c3);
    cudaGetSymbolAddress((void**)&p_s0, d_sum0);
    cudaGetSymbolAddress((void**)&p_q0, d_sq0);
    cudaGetSymbolAddress((void**)&p_s1, d_sum1);
    cudaGetSymbolAddress((void**)&p_q1, d_sq1);
    cudaGetSymbolAddress((void**)&p_s2, d_sum2);
    cudaGetSymbolAddress((void**)&p_q2, d_sq2);

    k_detect<<<1, 128>>>((const unsigned*)ei, (const unsigned*)sm);    // 1
    k_maskcount<<<32, 256>>>(sm, smw);                                 // 2
    k_mask_scanfill<<<1, 512>>>();                                     // 3
    k_stageA<<<Nn / NPB, 512>>>(x, smb);                               // 4 <- ncu capture
    k_zero<<<(Nn + 255) / 256, 256>>>();                               // 5
    k_edges<<<(ENt + 255) / 256, 256>>>(ei, ew);                       // 6
    k_scan_dinv<<<1, 1024>>>();                                        // 7
    k_fill<<<(ENt + 255) / 256, 256>>>(ew);                            // 8

    k_stats<<<256, 512>>>(p_h0, p_s0, p_q0, OMt);                      // 9
    k_prep<<<(OMt * C1t + 255) / 256 + 1, 256>>>(W1, p_s0, p_q0, bnsg, bnsb,
                                                 nullptr, p_W1f, p_c1, OMt, C1t);
    k_gemm<<<dim3((Nn + 127) / 128, C1t / 128), 256>>>(p_h0, p_W1f, p_g1, OMt, C1t);
    k_agg<<<Nn, C1t>>>(p_g1, p_c1, b1, p_h1, C1t);

    k_stats<<<256, 256>>>(p_h1, p_s1, p_q1, C1t);
    k_prep<<<(C1t * C2t + 255) / 256 + 1, 256>>>(W2, p_s1, p_q1, bn1g, bn1b,
                                                 nullptr, p_W2f, p_c2, C1t, C2t);
    k_gemm<<<dim3((Nn + 127) / 128, C2t / 128), 256>>>(p_h1, p_W2f, p_g2, C1t, C2t);
    k_agg<<<Nn, C2t>>>(p_g2, p_c2, b2, p_h2, C2t);

    k_stats<<<256, 128>>>(p_h2, p_s2, p_q2, C2t);
    k_prep<<<2, 256>>>(linW, p_s2, p_q2, bn2g, bn2b, linb, p_Wlf, p_c3, C2t, 2);
    k_final<<<(Nn + 7) / 8, 256>>>(out);
}

// round 9
// speedup vs baseline: 1.2547x; 1.0303x over previous
#include <cuda_runtime.h>

#define Nn   20000
#define PADR 128
#define Ee   640000
#define ENt  660000      // edges + self loops
#define INFt 2048
#define OMt  512
#define NCt  8192
#define C1t  256
#define C2t  128
#define EPSf 1e-5f

// ---------------- device scratch (static, no allocation) ----------------
__device__ int   g_ei64, g_sm64;
__device__ int   d_ROW[ENt], d_COL[ENt];
__device__ float d_deg[Nn], d_dinv[Nn];
__device__ int   d_ecnt[Nn], d_fillc[Nn], d_indptr[Nn + 1];
__device__ int   d_src[ENt];
__device__ float d_cw[ENt];
__device__ int   d_mcnt[OMt], d_mfill[OMt], d_mptr[OMt + 1];
__device__ int   d_min_[NCt], d_mout[NCt], d_sin[NCt];
__device__ float d_mw[NCt], d_sw[NCt];
__device__ float d_h0[(size_t)(Nn + PADR) * OMt];
__device__ float d_g1[(size_t)(Nn + PADR) * C1t], d_h1[(size_t)(Nn + PADR) * C1t];
__device__ float d_g2[(size_t)(Nn + PADR) * C2t], d_h2[(size_t)(Nn + PADR) * C2t];
__device__ float d_sum0[OMt], d_sq0[OMt], d_sum1[C1t], d_sq1[C1t], d_sum2[C2t], d_sq2[C2t];
__device__ float d_W1f[OMt * C1t], d_c1[C1t];
__device__ float d_W2f[C1t * C2t], d_c2[C2t];
__device__ float d_Wlf[C2t * 2],  d_c3[2];

// ---------------- 1: dtype sniff + zero mask counters ----------------
__global__ void k_detect(const unsigned* ei, const unsigned* sm) {
    __shared__ int f0, f1;
    int t = threadIdx.x;
    if (t == 0) { f0 = 0; f1 = 0; }
    __syncthreads();
    if (t < 128) {
        if (ei[2 * t + 1]) atomicOr(&f0, 1);
        if (sm[2 * t + 1]) atomicOr(&f1, 1);
    }
    for (int i = t; i < OMt; i += 128) { d_mcnt[i] = 0; d_mfill[i] = 0; }
    __syncthreads();
    if (t == 0) { g_ei64 = (f0 == 0); g_sm64 = (f1 == 0); }
}

// ---------------- 2: decode sparse mask + count per out column ----------------
__global__ void k_maskcount(const void* smv, const float* __restrict__ smw) {
    int j = blockIdx.x * blockDim.x + threadIdx.x;
    if (j >= NCt) return;
    int a, b;
    if (g_sm64) {
        const long long* p = (const long long*)smv;
        a = (int)p[2 * j]; b = (int)p[2 * j + 1];
    } else {
        const int* p = (const int*)smv;
        a = p[2 * j]; b = p[2 * j + 1];
    }
    d_min_[j] = a; d_mout[j] = b; d_mw[j] = smw[j];
    atomicAdd(&d_mcnt[b], 1);
}

// ---------------- 3: single block: scan 512 mask counts + CSC fill ----------------
__global__ void __launch_bounds__(512) k_mask_scanfill() {
    __shared__ int wsum[16];
    int t = threadIdx.x;
    int lane = t & 31, warp = t >> 5;
    int v = d_mcnt[t];
    int s = v;
#pragma unroll
    for (int off = 1; off < 32; off <<= 1) {
        int u = __shfl_up_sync(~0u, s, off);
        if (lane >= off) s += u;
    }
    if (lane == 31) wsum[warp] = s;
    __syncthreads();
    if (warp == 0 && lane < 16) {
        int w = wsum[lane];
#pragma unroll
        for (int off = 1; off < 16; off <<= 1) {
            int u = __shfl_up_sync(0xffffu, w, off);
            if (lane >= off) w += u;
        }
        wsum[lane] = w;
    }
    __syncthreads();
    int incl = s + (warp ? wsum[warp - 1] : 0);
    d_mptr[t] = incl - v;
    if (t == 511) d_mptr[OMt] = incl;
    __syncthreads();
    for (int j = t; j < NCt; j += 512) {
        int b = d_mout[j];
        int p = d_mptr[b] + atomicAdd(&d_mfill[b], 1);
        d_sin[p] = d_min_[j];
        d_sw[p] = d_mw[j];
    }
}

// ---------------- 4 (PROFILED): sparse masked linear + ReLU ----------------
// xs4[f] packs the 4 nodes' values for feature f -> one LDS.128 per connection
// instead of 4 scalar LDS.32 at the same random bank.
#define NPB 4
__global__ void __launch_bounds__(512) k_stageA(const float* __restrict__ x,
                                                const float* __restrict__ smb) {
    __shared__ float4 xs4[INFt];
    int node0 = blockIdx.x * NPB;
    int t = threadIdx.x;
    const float* x0 = x + (size_t)node0 * INFt;
#pragma unroll
    for (int i = 0; i < INFt / 512; i++) {
        int f = t + i * 512;
        float4 v;
        v.x = __ldg(&x0[f]);
        v.y = __ldg(&x0[f + INFt]);
        v.z = __ldg(&x0[f + 2 * INFt]);
        v.w = __ldg(&x0[f + 3 * INFt]);
        xs4[f] = v;
    }
    __syncthreads();
    int o = t;
    float a0 = 0.f, a1 = 0.f, a2 = 0.f, a3 = 0.f;
    int p0 = d_mptr[o], p1 = d_mptr[o + 1];
    for (int p = p0; p < p1; p++) {
        int idx = d_sin[p];
        float w = d_sw[p];
        float4 v = xs4[idx];
        a0 += v.x * w;
        a1 += v.y * w;
        a2 += v.z * w;
        a3 += v.w * w;
    }
    float b = smb[o];
    d_h0[(size_t)(node0 + 0) * OMt + o] = fmaxf(a0 + b, 0.f);
    d_h0[(size_t)(node0 + 1) * OMt + o] = fmaxf(a1 + b, 0.f);
    d_h0[(size_t)(node0 + 2) * OMt + o] = fmaxf(a2 + b, 0.f);
    d_h0[(size_t)(node0 + 3) * OMt + o] = fmaxf(a3 + b, 0.f);
}

// ---------------- 5: zero edge counters + BN accumulators ----------------
__global__ void k_zero() {
    int i = blockIdx.x * blockDim.x + threadIdx.x;
    if (i < Nn)  { d_deg[i] = 0.f; d_ecnt[i] = 0; d_fillc[i] = 0; }
    if (i < OMt) { d_sum0[i] = 0.f; d_sq0[i] = 0.f; }
    if (i < C1t) { d_sum1[i] = 0.f; d_sq1[i] = 0.f; }
    if (i < C2t) { d_sum2[i] = 0.f; d_sq2[i] = 0.f; }
}

// ---------------- 6: decode edges + per-col degree/count ----------------
__global__ void k_edges(const void* eiv, const float* __restrict__ ew) {
    int e = blockIdx.x * blockDim.x + threadIdx.x;
    if (e >= ENt) return;
    int r, c;
    if (e < Ee) {
        if (g_ei64) {
            const long long* p = (const long long*)eiv;
            r = (int)p[e]; c = (int)p[Ee + e];
        } else {
            const int* p = (const int*)eiv;
            r = p[e]; c = p[Ee + e];
        }
    } else { r = c = e - Ee; }
    float w = (e < Ee) ? ew[e] : 1.f;
    d_ROW[e] = r; d_COL[e] = c;
    atomicAdd(&d_deg[c], w);
    atomicAdd(&d_ecnt[c], 1);
}

// ---------------- 7: shuffle-scan indptr (20000) + dinv ----------------
__global__ void __launch_bounds__(1024) k_scan_dinv() {
    __shared__ int wsum[32];
    const int CH = 20;
    int t = threadIdx.x;
    int lane = t & 31, warp = t >> 5;
    int base = t * CH;
    int cnts[CH];
    int loc = 0;
#pragma unroll
    for (int i = 0; i < CH; i++) {
        int v = (base + i < Nn) ? __ldg(&d_ecnt[base + i]) : 0;
        cnts[i] = v; loc += v;
    }
    int s = loc;
#pragma unroll
    for (int off = 1; off < 32; off <<= 1) {
        int u = __shfl_up_sync(~0u, s, off);
        if (lane >= off) s += u;
    }
    if (lane == 31) wsum[warp] = s;
    __syncthreads();
    if (warp == 0) {
        int w = wsum[lane];
#pragma unroll
        for (int off = 1; off < 32; off <<= 1) {
            int u = __shfl_up_sync(~0u, w, off);
            if (lane >= off) w += u;
        }
        wsum[lane] = w;
    }
    __syncthreads();
    int run = s - loc + (warp ? wsum[warp - 1] : 0);
#pragma unroll
    for (int i = 0; i < CH; i++) {
        if (base + i < Nn) d_indptr[base + i] = run;
        run += cnts[i];
    }
    if (t == 1023) d_indptr[Nn] = run;
    for (int i = t; i < Nn; i += 1024) {
        float dg = d_deg[i];
        d_dinv[i] = (dg > 0.f) ? rsqrtf(dg) : 0.f;
    }
}

// ---------------- 8: CSR fill with normalized weights ----------------
__global__ void k_fill(const float* __restrict__ ew) {
    int e = blockIdx.x * blockDim.x + threadIdx.x;
    if (e >= ENt) return;
    int c = d_COL[e], r = d_ROW[e];
    int p = d_indptr[c] + atomicAdd(&d_fillc[c], 1);
    float w = (e < Ee) ? ew[e] : 1.f;
    d_src[p] = r;
    d_cw[p] = d_dinv[r] * w * d_dinv[c];
}

// ---------------- column stats (low-contention: 256 blocks) ----------------
__global__ void k_stats(const float* __restrict__ in, float* __restrict__ sum,
                        float* __restrict__ sq, int F) {
    int t = threadIdx.x;   // blockDim == F
    float s = 0.f, q = 0.f;
    for (int r = blockIdx.x; r < Nn; r += gridDim.x) {
        float v = in[(size_t)r * F + t];
        s += v; q += v * v;
    }
    atomicAdd(&sum[t], s);
    atomicAdd(&sq[t], q);
}

// ---------------- merged BN-fold: Wf = a⊙W (rows), c = d@W (+addb) ----------------
__global__ void __launch_bounds__(256) k_prep(
    const float* __restrict__ W, const float* __restrict__ sum,
    const float* __restrict__ sq, const float* __restrict__ g,
    const float* __restrict__ b, const float* __restrict__ addb,
    float* __restrict__ Wf, float* __restrict__ cvec, int Kd, int Nd) {
    int t = threadIdx.x;
    if (blockIdx.x + 1 < gridDim.x) {
        int i = blockIdx.x * 256 + t;
        if (i < Kd * Nd) {
            int k = i / Nd;
            float m = sum[k] * (1.f / Nn);
            float v = fmaxf(sq[k] * (1.f / Nn) - m * m, 0.f);
            float s = g[k] * rsqrtf(v + EPSf);
            Wf[i] = s * W[i];
        }
    } else {
        __shared__ float dsh[512];
        for (int k = t; k < Kd; k += 256) {
            float m = sum[k] * (1.f / Nn);
            float v = fmaxf(sq[k] * (1.f / Nn) - m * m, 0.f);
            float s = g[k] * rsqrtf(v + EPSf);
            dsh[k] = b[k] - m * s;
        }
        __syncthreads();
        if (t < Nd) {
            float s = addb ? addb[t] : 0.f;
            for (int k = 0; k < Kd; k++) s += dsh[k] * W[k * Nd + t];
            cvec[t] = s;
        }
    }
}

// ---------------- SGEMM: C[M,Nd] = A[M,K]@B[K,Nd]  (128x128 tile, 8x8 micro) ----------------
// A, C padded to Nn+PADR rows -> no row guards.
__global__ void __launch_bounds__(256, 2)
k_gemm(const float* __restrict__ A, const float* __restrict__ B,
       float* __restrict__ C, int K, int Nd) {
    __shared__ __align__(16) float As[16][128];
    __shared__ __align__(16) float Bs[16][128];
    int t = threadIdx.x;
    int tx = t & 15, ty = t >> 4;
    int mb = blockIdx.x * 128, nb = blockIdx.y * 128;
    float c[8][8];
#pragma unroll
    for (int i = 0; i < 8; i++)
#pragma unroll
        for (int j = 0; j < 8; j++) c[i][j] = 0.f;

    for (int kt = 0; kt < K; kt += 16) {
#pragma unroll
        for (int i = 0; i < 2; i++) {
            int li = t + i * 256;
            int row = li >> 2, kq = li & 3;
            float4 v = *(const float4*)(A + (size_t)(mb + row) * K + kt + kq * 4);
            int kk = kq * 4;
            As[kk + 0][row] = v.x;
            As[kk + 1][row] = v.y;
            As[kk + 2][row] = v.z;
            As[kk + 3][row] = v.w;
        }
#pragma unroll
        for (int i = 0; i < 2; i++) {
            int li = t + i * 256;
            int kr = li >> 5, jq = li & 31;
            *(float4*)&Bs[kr][jq * 4] =
                *(const float4*)(B + (size_t)(kt + kr) * Nd + nb + jq * 4);
        }
        __syncthreads();
#pragma unroll
        for (int k = 0; k < 16; k++) {
            float4 a0 = *(const float4*)&As[k][ty * 8];
            float4 a1 = *(const float4*)&As[k][ty * 8 + 4];
            float4 b0 = *(const float4*)&Bs[k][tx * 8];
            float4 b1 = *(const float4*)&Bs[k][tx * 8 + 4];
            float av[8] = {a0.x, a0.y, a0.z, a0.w, a1.x, a1.y, a1.z, a1.w};
            float bv[8] = {b0.x, b0.y, b0.z, b0.w, b1.x, b1.y, b1.z, b1.w};
#pragma unroll
            for (int i = 0; i < 8; i++)
#pragma unroll
                for (int j = 0; j < 8; j++) c[i][j] = fmaf(av[i], bv[j], c[i][j]);
        }
        __syncthreads();
    }
#pragma unroll
    for (int i = 0; i < 8; i++) {
        int m = mb + ty * 8 + i;
#pragma unroll
        for (int j = 0; j < 2; j++) {
            int col = nb + tx * 8 + j * 4;
            *(float4*)(C + (size_t)m * Nd + col) = *(float4*)&c[i][j * 4];
        }
    }
}

// ---------------- CSR agg: out[n] = relu(sum w*g[src] + (sum w)*cv + bias) ----------------
__global__ void k_agg(const float* __restrict__ g, const float* __restrict__ cv,
                      const float* __restrict__ bias, float* __restrict__ out, int F) {
    int n = blockIdx.x, t = threadIdx.x;
    int s0 = d_indptr[n], s1 = d_indptr[n + 1];
    float acc = 0.f, ws = 0.f;
    for (int e = s0; e < s1; e++) {
        int s = __ldg(&d_src[e]);
        float w = __ldg(&d_cw[e]);
        ws += w;
        acc += g[(size_t)s * F + t] * w;
    }
    out[(size_t)n * F + t] = fmaxf(acc + ws * cv[t] + bias[t], 0.f);
}

// ---------------- final linear: out[n,:2] = h2[n,:] @ Wlf + c3 ----------------
__global__ void k_final(float* __restrict__ out) {
    int w = blockIdx.x * 8 + (threadIdx.x >> 5);
    int lane = threadIdx.x & 31;
    if (w >= Nn) return;
    float4 v = ((const float4*)(d_h2 + (size_t)w * C2t))[lane];
    float4 w0 = ((const float4*)d_Wlf)[lane * 2];
    float4 w1 = ((const float4*)d_Wlf)[lane * 2 + 1];
    float s0 = v.x * w0.x + v.y * w0.z + v.z * w1.x + v.w * w1.z;
    float s1 = v.x * w0.y + v.y * w0.w + v.z * w1.y + v.w * w1.w;
#pragma unroll
    for (int off = 16; off; off >>= 1) {
        s0 += __shfl_down_sync(0xffffffffu, s0, off);
        s1 += __shfl_down_sync(0xffffffffu, s1, off);
    }
    if (lane == 0) {
        out[w * 2 + 0] = s0 + d_c3[0];
        out[w * 2 + 1] = s1 + d_c3[1];
    }
}

// ---------------- host launch ----------------
extern "C" void kernel_launch(void* const* d_in, const int* in_sizes, int n_in,
                              void* d_out, int out_size) {
    const float* x     = (const float*)d_in[0];
    const void*  ei    = d_in[1];
    const float* ew    = (const float*)d_in[2];
    const void*  sm    = d_in[3];
    const float* smw   = (const float*)d_in[4];
    const float* smb   = (const float*)d_in[5];
    const float* bnsg  = (const float*)d_in[6];
    const float* bnsb  = (const float*)d_in[7];
    const float* W1    = (const float*)d_in[8];
    const float* b1    = (const float*)d_in[9];
    const float* bn1g  = (const float*)d_in[10];
    const float* bn1b  = (const float*)d_in[11];
    const float* W2    = (const float*)d_in[12];
    const float* b2    = (const float*)d_in[13];
    const float* bn2g  = (const float*)d_in[14];
    const float* bn2b  = (const float*)d_in[15];
    const float* linW  = (const float*)d_in[16];
    const float* linb  = (const float*)d_in[17];
    float* out = (float*)d_out;

    float *p_h0, *p_g1, *p_h1, *p_g2, *p_h2;
    float *p_W1f, *p_W2f, *p_Wlf, *p_c1, *p_c2, *p_c3;
    float *p_s0, *p_q0, *p_s1, *p_q1, *p_s2, *p_q2;
    cudaGetSymbolAddress((void**)&p_h0, d_h0);
    cudaGetSymbolAddress((void**)&p_g1, d_g1);
    cudaGetSymbolAddress((void**)&p_h1, d_h1);
    cudaGetSymbolAddress((void**)&p_g2, d_g2);
    cudaGetSymbolAddress((void**)&p_h2, d_h2);
    cudaGetSymbolAddress((void**)&p_W1f, d_W1f);
    cudaGetSymbolAddress((void**)&p_W2f, d_W2f);
    cudaGetSymbolAddress((void**)&p_Wlf, d_Wlf);
    cudaGetSymbolAddress((void**)&p_c1, d_c1);
    cudaGetSymbolAddress((void**)&p_c2, d_c2);
    cudaGetSymbolAddress((void**)&p_c3, d_c3);
    cudaGetSymbolAddress((void**)&p_s0, d_sum0);
    cudaGetSymbolAddress((void**)&p_q0, d_sq0);
    cudaGetSymbolAddress((void**)&p_s1, d_sum1);
    cudaGetSymbolAddress((void**)&p_q1, d_sq1);
    cudaGetSymbolAddress((void**)&p_s2, d_sum2);
    cudaGetSymbolAddress((void**)&p_q2, d_sq2);

    k_detect<<<1, 128>>>((const unsigned*)ei, (const unsigned*)sm);    // 1
    k_maskcount<<<32, 256>>>(sm, smw);                                 // 2
    k_mask_scanfill<<<1, 512>>>();                                     // 3
    k_stageA<<<Nn / NPB, 512>>>(x, smb);                               // 4 <- ncu capture
    k_zero<<<(Nn + 255) / 256, 256>>>();                               // 5
    k_edges<<<(ENt + 255) / 256, 256>>>(ei, ew);                       // 6
    k_scan_dinv<<<1, 1024>>>();                                        // 7
    k_fill<<<(ENt + 255) / 256, 256>>>(ew);                            // 8

    k_stats<<<256, 512>>>(p_h0, p_s0, p_q0, OMt);                      // 9
    k_prep<<<(OMt * C1t + 255) / 256 + 1, 256>>>(W1, p_s0, p_q0, bnsg, bnsb,
                                                 nullptr, p_W1f, p_c1, OMt, C1t);
    k_gemm<<<dim3((Nn + 127) / 128, C1t / 128), 256>>>(p_h0, p_W1f, p_g1, OMt, C1t);
    k_agg<<<Nn, C1t>>>(p_g1, p_c1, b1, p_h1, C1t);

    k_stats<<<256, 256>>>(p_h1, p_s1, p_q1, C1t);
    k_prep<<<(C1t * C2t + 255) / 256 + 1, 256>>>(W2, p_s1, p_q1, bn1g, bn1b,
                                                 nullptr, p_W2f, p_c2, C1t, C2t);
    k_gemm<<<dim3((Nn + 127) / 128, C2t / 128), 256>>>(p_h1, p_W2f, p_g2, C1t, C2t);
    k_agg<<<Nn, C2t>>>(p_g2, p_c2, b2, p_h2, C2t);

    k_stats<<<256, 128>>>(p_h2, p_s2, p_q2, C2t);
    k_prep<<<2, 256>>>(linW, p_s2, p_q2, bn2g, bn2b, linb, p_Wlf, p_c3, C2t, 2);
    k_final<<<(Nn + 7) / 8, 256>>>(out);
}